// round 1
// baseline (speedup 1.0000x reference)
#include <cuda_runtime.h>
#include <cuda_bf16.h>
#include <math.h>

// ---------------------------------------------------------------------------
// EncoderLayer: B=2, S=2048, D=1024, H=16, dk=64, FF=4096, fp32
// Round 0: correct fp32 baseline.
//   - 128x128x16 register-tiled SGEMM with fused bias/scale/relu/residual
//   - streaming flash-attention (64-query tiles, online softmax)
//   - block-per-row LayerNorm
// ---------------------------------------------------------------------------

#define D_MODEL 1024
#define SEQ     2048
#define BATCH   2
#define NHEADS  16
#define DK      64
#define DFF     4096
#define MTOT    (BATCH * SEQ)          // 4096 rows

// Scratch (device globals — no allocation allowed)
__device__ float g_Q  [MTOT * D_MODEL];
__device__ float g_K  [MTOT * D_MODEL];
__device__ float g_V  [MTOT * D_MODEL];
__device__ float g_ctx[MTOT * D_MODEL];
__device__ float g_t1 [MTOT * D_MODEL];
__device__ float g_x1 [MTOT * D_MODEL];
__device__ float g_h1 [MTOT * DFF];
__device__ float g_t2 [MTOT * D_MODEL];

// ---------------------------------------------------------------------------
// SGEMM: C[M,N] = act( (A[M,K] @ W[K,N] + bias) * scale ) + residual
// BM=BN=128, BK=16, 256 threads, 8x8 per thread.
// ---------------------------------------------------------------------------
#define BM 128
#define BN 128
#define BK 16

__global__ void __launch_bounds__(256)
gemm_kernel(const float* __restrict__ A, const float* __restrict__ W,
            const float* __restrict__ bias, const float* __restrict__ res,
            float* __restrict__ C, int M, int N, int K, float scale, int relu)
{
    __shared__ float As[BK][BM];
    __shared__ float Bs[BK][BN];

    const int tid = threadIdx.x;
    const int tx = tid & 15;
    const int ty = tid >> 4;
    const int bm = blockIdx.y * BM;
    const int bn = blockIdx.x * BN;

    const float* Aptr = A + (size_t)bm * K;
    const float* Wptr = W + bn;

    float acc[8][8];
#pragma unroll
    for (int i = 0; i < 8; i++)
#pragma unroll
        for (int j = 0; j < 8; j++) acc[i][j] = 0.f;

    for (int k0 = 0; k0 < K; k0 += BK) {
        // Load A tile (128x16) transposed into As[k][m]
#pragma unroll
        for (int l = 0; l < 2; l++) {
            int idx = tid + l * 256;      // 0..511
            int r = idx >> 2;             // row 0..127
            int c4 = idx & 3;             // float4 index within row
            float4 v = *(const float4*)(Aptr + (size_t)r * K + k0 + c4 * 4);
            As[c4 * 4 + 0][r] = v.x;
            As[c4 * 4 + 1][r] = v.y;
            As[c4 * 4 + 2][r] = v.z;
            As[c4 * 4 + 3][r] = v.w;
        }
        // Load B tile (16x128)
#pragma unroll
        for (int l = 0; l < 2; l++) {
            int idx = tid + l * 256;
            int r = idx >> 5;             // 0..15
            int c4 = idx & 31;            // 0..31
            *(float4*)(&Bs[r][c4 * 4]) =
                *(const float4*)(Wptr + (size_t)(k0 + r) * N + c4 * 4);
        }
        __syncthreads();

#pragma unroll
        for (int kk = 0; kk < BK; kk++) {
            float a[8], b[8];
            *(float4*)(a)     = *(const float4*)(&As[kk][ty * 8]);
            *(float4*)(a + 4) = *(const float4*)(&As[kk][ty * 8 + 4]);
            *(float4*)(b)     = *(const float4*)(&Bs[kk][tx * 8]);
            *(float4*)(b + 4) = *(const float4*)(&Bs[kk][tx * 8 + 4]);
#pragma unroll
            for (int i = 0; i < 8; i++)
#pragma unroll
                for (int j = 0; j < 8; j++)
                    acc[i][j] = fmaf(a[i], b[j], acc[i][j]);
        }
        __syncthreads();
    }

    // Epilogue
    float bcol[8];
#pragma unroll
    for (int j = 0; j < 8; j++) bcol[j] = bias[bn + tx * 8 + j];

#pragma unroll
    for (int i = 0; i < 8; i++) {
        int row = bm + ty * 8 + i;
        size_t base = (size_t)row * N + bn + tx * 8;
        float out[8];
#pragma unroll
        for (int j = 0; j < 8; j++) {
            float v = (acc[i][j] + bcol[j]) * scale;
            if (relu) v = fmaxf(v, 0.f);
            out[j] = v;
        }
        if (res) {
#pragma unroll
            for (int j = 0; j < 8; j++) out[j] += res[base + j];
        }
        *(float4*)(&C[base])     = *(float4*)(out);
        *(float4*)(&C[base + 4]) = *(float4*)(out + 4);
    }
}

// ---------------------------------------------------------------------------
// Flash attention (fp32): one CTA per (q-block of 64, head, batch).
// Q already scaled by 1/sqrt(dk). Layouts: [B, S, H*dk].
// ---------------------------------------------------------------------------
#define FP 65   // smem row pad

__global__ void __launch_bounds__(256)
flash_kernel(const float* __restrict__ Qg, const float* __restrict__ Kg,
             const float* __restrict__ Vg, float* __restrict__ ctx)
{
    extern __shared__ float sm[];
    float* Qs  = sm;                 // [64][FP]  Qs[q][d]
    float* Ks  = Qs + 64 * FP;       // [64][FP]  Ks[d][k]   (transposed)
    float* Vs  = Ks + 64 * FP;       // [64][FP]  Vs[k][d]
    float* Ss  = Vs + 64 * FP;       // [64][FP]  scores / probs
    float* ms  = Ss + 64 * FP;       // [64] running max
    float* ls  = ms + 64;            // [64] running sum
    float* aS  = ls + 64;            // [64] alpha
    float* red = aS + 64;            // [64][4]

    const int tid = threadIdx.x;
    const int tx = tid & 15;
    const int ty = tid >> 4;
    const int qb = blockIdx.x;
    const int h  = blockIdx.y;
    const int b  = blockIdx.z;

    const size_t baseQ  = ((size_t)b * SEQ + (size_t)qb * 64) * D_MODEL + h * DK;
    const size_t baseKV = ((size_t)b * SEQ) * D_MODEL + h * DK;

    for (int i = tid; i < 64 * 64; i += 256) {
        int r = i >> 6, d = i & 63;
        Qs[r * FP + d] = Qg[baseQ + (size_t)r * D_MODEL + d];
    }
    if (tid < 64) { ms[tid] = -1e30f; ls[tid] = 0.f; }

    float o[4][4];
#pragma unroll
    for (int i = 0; i < 4; i++)
#pragma unroll
        for (int j = 0; j < 4; j++) o[i][j] = 0.f;

    __syncthreads();

    for (int kb = 0; kb < SEQ / 64; kb++) {
        const size_t baseK = baseKV + (size_t)kb * 64 * D_MODEL;
        for (int i = tid; i < 64 * 64; i += 256) {
            int r = i >> 6, d = i & 63;
            float kv = Kg[baseK + (size_t)r * D_MODEL + d];
            float vv = Vg[baseK + (size_t)r * D_MODEL + d];
            Ks[d * FP + r] = kv;     // transposed, conflict-free (FP odd)
            Vs[r * FP + d] = vv;
        }
        __syncthreads();

        // Scores: 4x4 per thread over 64x64
        float s4[4][4];
#pragma unroll
        for (int i = 0; i < 4; i++)
#pragma unroll
            for (int j = 0; j < 4; j++) s4[i][j] = 0.f;

#pragma unroll 8
        for (int d = 0; d < 64; d++) {
            float a0 = Qs[(ty * 4 + 0) * FP + d];
            float a1 = Qs[(ty * 4 + 1) * FP + d];
            float a2 = Qs[(ty * 4 + 2) * FP + d];
            float a3 = Qs[(ty * 4 + 3) * FP + d];
            float b0 = Ks[d * FP + tx * 4 + 0];
            float b1 = Ks[d * FP + tx * 4 + 1];
            float b2 = Ks[d * FP + tx * 4 + 2];
            float b3 = Ks[d * FP + tx * 4 + 3];
            s4[0][0] = fmaf(a0, b0, s4[0][0]); s4[0][1] = fmaf(a0, b1, s4[0][1]);
            s4[0][2] = fmaf(a0, b2, s4[0][2]); s4[0][3] = fmaf(a0, b3, s4[0][3]);
            s4[1][0] = fmaf(a1, b0, s4[1][0]); s4[1][1] = fmaf(a1, b1, s4[1][1]);
            s4[1][2] = fmaf(a1, b2, s4[1][2]); s4[1][3] = fmaf(a1, b3, s4[1][3]);
            s4[2][0] = fmaf(a2, b0, s4[2][0]); s4[2][1] = fmaf(a2, b1, s4[2][1]);
            s4[2][2] = fmaf(a2, b2, s4[2][2]); s4[2][3] = fmaf(a2, b3, s4[2][3]);
            s4[3][0] = fmaf(a3, b0, s4[3][0]); s4[3][1] = fmaf(a3, b1, s4[3][1]);
            s4[3][2] = fmaf(a3, b2, s4[3][2]); s4[3][3] = fmaf(a3, b3, s4[3][3]);
        }
#pragma unroll
        for (int i = 0; i < 4; i++)
#pragma unroll
            for (int j = 0; j < 4; j++)
                Ss[(ty * 4 + i) * FP + tx * 4 + j] = s4[i][j];
        __syncthreads();

        // Row max (4 threads per row)
        {
            int r = tid & 63, q = tid >> 6;
            float mx = -1e30f;
#pragma unroll
            for (int c = 0; c < 16; c++) mx = fmaxf(mx, Ss[r * FP + q * 16 + c]);
            red[r * 4 + q] = mx;
        }
        __syncthreads();
        if (tid < 64) {
            int r = tid;
            float mnew = fmaxf(fmaxf(red[r * 4 + 0], red[r * 4 + 1]),
                               fmaxf(red[r * 4 + 2], red[r * 4 + 3]));
            mnew = fmaxf(mnew, ms[r]);
            float alpha = __expf(ms[r] - mnew);
            aS[r] = alpha;
            ls[r] *= alpha;
            ms[r] = mnew;
        }
        __syncthreads();
        // exp + partial row sums
        {
            int r = tid & 63, q = tid >> 6;
            float mrow = ms[r];
            float ssum = 0.f;
#pragma unroll
            for (int c = 0; c < 16; c++) {
                float p = __expf(Ss[r * FP + q * 16 + c] - mrow);
                Ss[r * FP + q * 16 + c] = p;
                ssum += p;
            }
            red[r * 4 + q] = ssum;
        }
        __syncthreads();
        if (tid < 64)
            ls[tid] += red[tid * 4 + 0] + red[tid * 4 + 1] +
                       red[tid * 4 + 2] + red[tid * 4 + 3];

        // Rescale O and accumulate P @ V
        float al[4];
#pragma unroll
        for (int i = 0; i < 4; i++) al[i] = aS[ty * 4 + i];
#pragma unroll
        for (int i = 0; i < 4; i++)
#pragma unroll
            for (int j = 0; j < 4; j++) o[i][j] *= al[i];

#pragma unroll 8
        for (int k = 0; k < 64; k++) {
            float p0 = Ss[(ty * 4 + 0) * FP + k];
            float p1 = Ss[(ty * 4 + 1) * FP + k];
            float p2 = Ss[(ty * 4 + 2) * FP + k];
            float p3 = Ss[(ty * 4 + 3) * FP + k];
            float v0 = Vs[k * FP + tx * 4 + 0];
            float v1 = Vs[k * FP + tx * 4 + 1];
            float v2 = Vs[k * FP + tx * 4 + 2];
            float v3 = Vs[k * FP + tx * 4 + 3];
            o[0][0] = fmaf(p0, v0, o[0][0]); o[0][1] = fmaf(p0, v1, o[0][1]);
            o[0][2] = fmaf(p0, v2, o[0][2]); o[0][3] = fmaf(p0, v3, o[0][3]);
            o[1][0] = fmaf(p1, v0, o[1][0]); o[1][1] = fmaf(p1, v1, o[1][1]);
            o[1][2] = fmaf(p1, v2, o[1][2]); o[1][3] = fmaf(p1, v3, o[1][3]);
            o[2][0] = fmaf(p2, v0, o[2][0]); o[2][1] = fmaf(p2, v1, o[2][1]);
            o[2][2] = fmaf(p2, v2, o[2][2]); o[2][3] = fmaf(p2, v3, o[2][3]);
            o[3][0] = fmaf(p3, v0, o[3][0]); o[3][1] = fmaf(p3, v1, o[3][1]);
            o[3][2] = fmaf(p3, v2, o[3][2]); o[3][3] = fmaf(p3, v3, o[3][3]);
        }
        __syncthreads();
    }

    float invl[4];
#pragma unroll
    for (int i = 0; i < 4; i++) invl[i] = 1.f / ls[ty * 4 + i];
#pragma unroll
    for (int i = 0; i < 4; i++)
#pragma unroll
        for (int j = 0; j < 4; j++)
            ctx[baseQ + (size_t)(ty * 4 + i) * D_MODEL + tx * 4 + j] =
                o[i][j] * invl[i];
}

// ---------------------------------------------------------------------------
// LayerNorm over last dim (1024). One block (256 threads) per row.
// ---------------------------------------------------------------------------
__global__ void __launch_bounds__(256)
ln_kernel(const float* __restrict__ x, const float* __restrict__ g,
          const float* __restrict__ bb, float* __restrict__ out)
{
    const int row = blockIdx.x;
    const int tid = threadIdx.x;
    const float4 v = ((const float4*)(x + (size_t)row * D_MODEL))[tid];

    float s  = v.x + v.y + v.z + v.w;
    float ss = fmaf(v.x, v.x, fmaf(v.y, v.y, fmaf(v.z, v.z, v.w * v.w)));

    __shared__ float rs[8], rss[8];
#pragma unroll
    for (int o = 16; o > 0; o >>= 1) {
        s  += __shfl_down_sync(0xFFFFFFFFu, s, o);
        ss += __shfl_down_sync(0xFFFFFFFFu, ss, o);
    }
    if ((tid & 31) == 0) { rs[tid >> 5] = s; rss[tid >> 5] = ss; }
    __syncthreads();
    if (tid == 0) {
        float S = 0.f, SS = 0.f;
#pragma unroll
        for (int i = 0; i < 8; i++) { S += rs[i]; SS += rss[i]; }
        rs[0] = S; rss[0] = SS;
    }
    __syncthreads();

    const float mu  = rs[0] * (1.f / D_MODEL);
    const float var = rss[0] * (1.f / D_MODEL) - mu * mu;
    const float inv = rsqrtf(var + 1e-5f);

    const float4 g4 = ((const float4*)g)[tid];
    const float4 b4 = ((const float4*)bb)[tid];
    float4 o4;
    o4.x = (v.x - mu) * inv * g4.x + b4.x;
    o4.y = (v.y - mu) * inv * g4.y + b4.y;
    o4.z = (v.z - mu) * inv * g4.z + b4.z;
    o4.w = (v.w - mu) * inv * g4.w + b4.w;
    ((float4*)(out + (size_t)row * D_MODEL))[tid] = o4;
}

// ---------------------------------------------------------------------------
// Launcher
// ---------------------------------------------------------------------------
extern "C" void kernel_launch(void* const* d_in, const int* in_sizes, int n_in,
                              void* d_out, int out_size)
{
    const float* src   = (const float*)d_in[0];
    const float* Wq    = (const float*)d_in[1];
    const float* bq    = (const float*)d_in[2];
    const float* Wk    = (const float*)d_in[3];
    const float* bk    = (const float*)d_in[4];
    const float* Wv    = (const float*)d_in[5];
    const float* bv    = (const float*)d_in[6];
    const float* Wo    = (const float*)d_in[7];
    const float* bo    = (const float*)d_in[8];
    const float* W1    = (const float*)d_in[9];
    const float* b1    = (const float*)d_in[10];
    const float* W2    = (const float*)d_in[11];
    const float* b2    = (const float*)d_in[12];
    const float* ln1g  = (const float*)d_in[13];
    const float* ln1b  = (const float*)d_in[14];
    const float* ln2g  = (const float*)d_in[15];
    const float* ln2b  = (const float*)d_in[16];
    float* out = (float*)d_out;

    float *Q, *K, *V, *ctx, *t1, *x1, *h1, *t2;
    cudaGetSymbolAddress((void**)&Q,   g_Q);
    cudaGetSymbolAddress((void**)&K,   g_K);
    cudaGetSymbolAddress((void**)&V,   g_V);
    cudaGetSymbolAddress((void**)&ctx, g_ctx);
    cudaGetSymbolAddress((void**)&t1,  g_t1);
    cudaGetSymbolAddress((void**)&x1,  g_x1);
    cudaGetSymbolAddress((void**)&h1,  g_h1);
    cudaGetSymbolAddress((void**)&t2,  g_t2);

    const int flash_smem = (4 * 64 * FP + 64 * 3 + 64 * 4) * (int)sizeof(float);
    cudaFuncSetAttribute(flash_kernel,
                         cudaFuncAttributeMaxDynamicSharedMemorySize, flash_smem);

    const float qscale = 0.125f;  // 1/sqrt(64)

    dim3 gProj(D_MODEL / BN, MTOT / BM);   // (8, 32)
    dim3 gFF1 (DFF / BN,     MTOT / BM);   // (32, 32)

    // QKV projections
    gemm_kernel<<<gProj, 256>>>(src, Wq, bq, nullptr, Q, MTOT, D_MODEL, D_MODEL, qscale, 0);
    gemm_kernel<<<gProj, 256>>>(src, Wk, bk, nullptr, K, MTOT, D_MODEL, D_MODEL, 1.f, 0);
    gemm_kernel<<<gProj, 256>>>(src, Wv, bv, nullptr, V, MTOT, D_MODEL, D_MODEL, 1.f, 0);

    // Attention
    dim3 gAtt(SEQ / 64, NHEADS, BATCH);
    flash_kernel<<<gAtt, 256, flash_smem>>>(Q, K, V, ctx);

    // Output projection + residual, LN1
    gemm_kernel<<<gProj, 256>>>(ctx, Wo, bo, src, t1, MTOT, D_MODEL, D_MODEL, 1.f, 0);
    ln_kernel<<<MTOT, 256>>>(t1, ln1g, ln1b, x1);

    // FFN
    gemm_kernel<<<gFF1, 256>>>(x1, W1, b1, nullptr, h1, MTOT, DFF, D_MODEL, 1.f, 1);
    gemm_kernel<<<gProj, 256>>>(h1, W2, b2, x1, t2, MTOT, D_MODEL, DFF, 1.f, 0);
    ln_kernel<<<MTOT, 256>>>(t2, ln2g, ln2b, out);
}

// round 3
// speedup vs baseline: 1.7632x; 1.7632x over previous
#include <cuda_runtime.h>
#include <cuda_bf16.h>
#include <cstdint>
#include <math.h>

// ---------------------------------------------------------------------------
// EncoderLayer: B=2, S=2048, D=1024, H=16, dk=64, FF=4096, fp32
// Round 3: GEMMs on mma.sync tf32 (sm_80-style HMMA path; tcgen05 is not
//          available at the harness's base sm_100 ptx target).
//          cp.async double-buffered 128x128x32 tiles, cvt.rna.tf32 fragments.
// ---------------------------------------------------------------------------

#define D_MODEL 1024
#define SEQ     2048
#define BATCH   2
#define NHEADS  16
#define DK      64
#define DFF     4096
#define MTOT    (BATCH * SEQ)          // 4096 rows

// Scratch (device globals — no allocation allowed)
__device__ float g_Q  [MTOT * D_MODEL];
__device__ float g_K  [MTOT * D_MODEL];
__device__ float g_V  [MTOT * D_MODEL];
__device__ float g_ctx[MTOT * D_MODEL];
__device__ float g_t1 [MTOT * D_MODEL];
__device__ float g_x1 [MTOT * D_MODEL];
__device__ float g_h1 [MTOT * DFF];
__device__ float g_t2 [MTOT * D_MODEL];

// ---------------------------------------------------------------------------
// tf32 MMA GEMM: C[M,N] = act((A[M,K] @ W[K,N] + bias)*scale) + residual
// BM=BN=128, BK=32, 256 thr (8 warps, 2x4 grid, 64x32 warp tile)
// ---------------------------------------------------------------------------
#define BM 128
#define BN 128
#define BK 32
#define APITCH 36            // floats; == 4 mod 32 -> conflict-free A frags
#define BPITCH 136           // floats; == 8 mod 32 -> conflict-free B frags
#define A_TILE (BM * APITCH) // 4608 floats
#define B_TILE (BK * BPITCH) // 4352 floats
#define SMEM_FLOATS (2 * (A_TILE + B_TILE))
#define GEMM_SMEM_BYTES (SMEM_FLOATS * 4)   // 71680

__device__ __forceinline__ void cp16(uint32_t saddr, const void* gptr) {
    asm volatile("cp.async.cg.shared.global [%0], [%1], 16;"
                 :: "r"(saddr), "l"(gptr));
}
__device__ __forceinline__ uint32_t smem_u32(const void* p) {
    uint32_t a;
    asm("{ .reg .u64 t; cvta.to.shared.u64 t, %1; cvt.u32.u64 %0, t; }"
        : "=r"(a) : "l"(p));
    return a;
}
__device__ __forceinline__ uint32_t to_tf32(float v) {
    uint32_t x;
    asm("cvt.rna.tf32.f32 %0, %1;" : "=r"(x) : "f"(v));
    return x;
}

__global__ void __launch_bounds__(256, 2)
gemm_tc(const float* __restrict__ A, const float* __restrict__ W,
        const float* __restrict__ bias, const float* __restrict__ res,
        float* __restrict__ C, int M, int N, int K, float scale, int relu)
{
    extern __shared__ float sm[];
    float* sA[2] = { sm,                         sm + A_TILE };
    float* sB[2] = { sm + 2 * A_TILE,            sm + 2 * A_TILE + B_TILE };

    const int tid = threadIdx.x;
    const int wid = tid >> 5;
    const int lid = tid & 31;
    const int g   = lid >> 2;       // group id (0..7)
    const int t   = lid & 3;        // thread in group (0..3)
    const int wm  = wid >> 2;       // 0..1  (warp m)
    const int wn  = wid & 3;        // 0..3  (warp n)
    const int bm  = blockIdx.y * BM;
    const int bn  = blockIdx.x * BN;

    float acc[4][4][4];             // [mi][ni][c]
#pragma unroll
    for (int mi = 0; mi < 4; mi++)
#pragma unroll
        for (int ni = 0; ni < 4; ni++)
#pragma unroll
            for (int c = 0; c < 4; c++) acc[mi][ni][c] = 0.f;

    const uint32_t sA_u[2] = { smem_u32(sA[0]), smem_u32(sA[1]) };
    const uint32_t sB_u[2] = { smem_u32(sB[0]), smem_u32(sB[1]) };

    // ---- async tile loaders --------------------------------------------
    auto load_tiles = [&](int buf, int k0) {
        // A: 128 rows x 32 floats (8 x 16B chunks/row) -> sA[m][k], pitch 36
#pragma unroll
        for (int l = 0; l < 4; l++) {
            int c  = tid + l * 256;       // 0..1023
            int r  = c >> 3;
            int sg = c & 7;
            cp16(sA_u[buf] + (uint32_t)(r * APITCH + sg * 4) * 4,
                 A + (size_t)(bm + r) * K + k0 + sg * 4);
        }
        // B: 32 rows x 128 floats (32 x 16B chunks/row) -> sB[k][n], pitch 136
#pragma unroll
        for (int l = 0; l < 4; l++) {
            int c  = tid + l * 256;
            int r  = c >> 5;
            int sg = c & 31;
            cp16(sB_u[buf] + (uint32_t)(r * BPITCH + sg * 4) * 4,
                 W + (size_t)(k0 + r) * N + bn + sg * 4);
        }
    };

    const int niter = K / BK;
    load_tiles(0, 0);
    asm volatile("cp.async.commit_group;" ::: "memory");

    for (int it = 0; it < niter; it++) {
        asm volatile("cp.async.wait_group 0;" ::: "memory");
        __syncthreads();

        if (it + 1 < niter) load_tiles((it + 1) & 1, (it + 1) * BK);
        asm volatile("cp.async.commit_group;" ::: "memory");

        const float* As = sA[it & 1];
        const float* Bs = sB[it & 1];
        const int mrow = wm * 64;
        const int ncol = wn * 32;

#pragma unroll
        for (int kk = 0; kk < 4; kk++) {
            const int kb = kk * 8;
            uint32_t af[4][4], bf[4][2];
#pragma unroll
            for (int mi = 0; mi < 4; mi++) {
                const float* ap = As + (mrow + mi * 16 + g) * APITCH + kb + t;
                af[mi][0] = to_tf32(ap[0]);
                af[mi][1] = to_tf32(ap[8 * APITCH]);
                af[mi][2] = to_tf32(ap[4]);
                af[mi][3] = to_tf32(ap[8 * APITCH + 4]);
            }
#pragma unroll
            for (int ni = 0; ni < 4; ni++) {
                const float* bp = Bs + (kb + t) * BPITCH + ncol + ni * 8 + g;
                bf[ni][0] = to_tf32(bp[0]);
                bf[ni][1] = to_tf32(bp[4 * BPITCH]);
            }
#pragma unroll
            for (int mi = 0; mi < 4; mi++)
#pragma unroll
                for (int ni = 0; ni < 4; ni++) {
                    asm volatile(
                        "mma.sync.aligned.m16n8k8.row.col.f32.tf32.tf32.f32 "
                        "{%0,%1,%2,%3}, {%4,%5,%6,%7}, {%8,%9}, {%0,%1,%2,%3};"
                        : "+f"(acc[mi][ni][0]), "+f"(acc[mi][ni][1]),
                          "+f"(acc[mi][ni][2]), "+f"(acc[mi][ni][3])
                        : "r"(af[mi][0]), "r"(af[mi][1]),
                          "r"(af[mi][2]), "r"(af[mi][3]),
                          "r"(bf[ni][0]), "r"(bf[ni][1]));
                }
        }
        __syncthreads();
    }

    // ---- epilogue -------------------------------------------------------
#pragma unroll
    for (int mi = 0; mi < 4; mi++) {
        const int r0 = bm + wm * 64 + mi * 16 + g;
        const int r1 = r0 + 8;
#pragma unroll
        for (int ni = 0; ni < 4; ni++) {
            const int c0 = bn + wn * 32 + ni * 8 + 2 * t;
            const float b0 = bias[c0], b1 = bias[c0 + 1];

            float v00 = (acc[mi][ni][0] + b0) * scale;
            float v01 = (acc[mi][ni][1] + b1) * scale;
            float v10 = (acc[mi][ni][2] + b0) * scale;
            float v11 = (acc[mi][ni][3] + b1) * scale;
            if (relu) {
                v00 = fmaxf(v00, 0.f); v01 = fmaxf(v01, 0.f);
                v10 = fmaxf(v10, 0.f); v11 = fmaxf(v11, 0.f);
            }
            if (res) {
                float2 q0 = *(const float2*)(res + (size_t)r0 * N + c0);
                float2 q1 = *(const float2*)(res + (size_t)r1 * N + c0);
                v00 += q0.x; v01 += q0.y; v10 += q1.x; v11 += q1.y;
            }
            *(float2*)(C + (size_t)r0 * N + c0) = make_float2(v00, v01);
            *(float2*)(C + (size_t)r1 * N + c0) = make_float2(v10, v11);
        }
    }
}

// ---------------------------------------------------------------------------
// Flash attention (fp32): one CTA per (q-block of 64, head, batch).
// Q already scaled by 1/sqrt(dk). Layouts: [B, S, H*dk].
// ---------------------------------------------------------------------------
#define FP 65   // smem row pad

__global__ void __launch_bounds__(256)
flash_kernel(const float* __restrict__ Qg, const float* __restrict__ Kg,
             const float* __restrict__ Vg, float* __restrict__ ctx)
{
    extern __shared__ float smf[];
    float* Qs  = smf;                // [64][FP]
    float* Ks  = Qs + 64 * FP;       // [64][FP] transposed
    float* Vs  = Ks + 64 * FP;       // [64][FP]
    float* Ss  = Vs + 64 * FP;       // [64][FP]
    float* ms  = Ss + 64 * FP;
    float* ls  = ms + 64;
    float* aS  = ls + 64;
    float* red = aS + 64;

    const int tid = threadIdx.x;
    const int tx = tid & 15;
    const int ty = tid >> 4;
    const int qb = blockIdx.x;
    const int h  = blockIdx.y;
    const int b  = blockIdx.z;

    const size_t baseQ  = ((size_t)b * SEQ + (size_t)qb * 64) * D_MODEL + h * DK;
    const size_t baseKV = ((size_t)b * SEQ) * D_MODEL + h * DK;

    for (int i = tid; i < 64 * 64; i += 256) {
        int r = i >> 6, d = i & 63;
        Qs[r * FP + d] = Qg[baseQ + (size_t)r * D_MODEL + d];
    }
    if (tid < 64) { ms[tid] = -1e30f; ls[tid] = 0.f; }

    float o[4][4];
#pragma unroll
    for (int i = 0; i < 4; i++)
#pragma unroll
        for (int j = 0; j < 4; j++) o[i][j] = 0.f;

    __syncthreads();

    for (int kb = 0; kb < SEQ / 64; kb++) {
        const size_t baseK = baseKV + (size_t)kb * 64 * D_MODEL;
        for (int i = tid; i < 64 * 64; i += 256) {
            int r = i >> 6, d = i & 63;
            Ks[d * FP + r] = Kg[baseK + (size_t)r * D_MODEL + d];
            Vs[r * FP + d] = Vg[baseK + (size_t)r * D_MODEL + d];
        }
        __syncthreads();

        float s4[4][4];
#pragma unroll
        for (int i = 0; i < 4; i++)
#pragma unroll
            for (int j = 0; j < 4; j++) s4[i][j] = 0.f;

#pragma unroll 8
        for (int d = 0; d < 64; d++) {
            float a0 = Qs[(ty * 4 + 0) * FP + d];
            float a1 = Qs[(ty * 4 + 1) * FP + d];
            float a2 = Qs[(ty * 4 + 2) * FP + d];
            float a3 = Qs[(ty * 4 + 3) * FP + d];
            float b0 = Ks[d * FP + tx * 4 + 0];
            float b1 = Ks[d * FP + tx * 4 + 1];
            float b2 = Ks[d * FP + tx * 4 + 2];
            float b3 = Ks[d * FP + tx * 4 + 3];
            s4[0][0] = fmaf(a0, b0, s4[0][0]); s4[0][1] = fmaf(a0, b1, s4[0][1]);
            s4[0][2] = fmaf(a0, b2, s4[0][2]); s4[0][3] = fmaf(a0, b3, s4[0][3]);
            s4[1][0] = fmaf(a1, b0, s4[1][0]); s4[1][1] = fmaf(a1, b1, s4[1][1]);
            s4[1][2] = fmaf(a1, b2, s4[1][2]); s4[1][3] = fmaf(a1, b3, s4[1][3]);
            s4[2][0] = fmaf(a2, b0, s4[2][0]); s4[2][1] = fmaf(a2, b1, s4[2][1]);
            s4[2][2] = fmaf(a2, b2, s4[2][2]); s4[2][3] = fmaf(a2, b3, s4[2][3]);
            s4[3][0] = fmaf(a3, b0, s4[3][0]); s4[3][1] = fmaf(a3, b1, s4[3][1]);
            s4[3][2] = fmaf(a3, b2, s4[3][2]); s4[3][3] = fmaf(a3, b3, s4[3][3]);
        }
#pragma unroll
        for (int i = 0; i < 4; i++)
#pragma unroll
            for (int j = 0; j < 4; j++)
                Ss[(ty * 4 + i) * FP + tx * 4 + j] = s4[i][j];
        __syncthreads();

        {
            int r = tid & 63, q = tid >> 6;
            float mx = -1e30f;
#pragma unroll
            for (int c = 0; c < 16; c++) mx = fmaxf(mx, Ss[r * FP + q * 16 + c]);
            red[r * 4 + q] = mx;
        }
        __syncthreads();
        if (tid < 64) {
            int r = tid;
            float mnew = fmaxf(fmaxf(red[r * 4 + 0], red[r * 4 + 1]),
                               fmaxf(red[r * 4 + 2], red[r * 4 + 3]));
            mnew = fmaxf(mnew, ms[r]);
            float alpha = __expf(ms[r] - mnew);
            aS[r] = alpha;
            ls[r] *= alpha;
            ms[r] = mnew;
        }
        __syncthreads();
        {
            int r = tid & 63, q = tid >> 6;
            float mrow = ms[r];
            float ssum = 0.f;
#pragma unroll
            for (int c = 0; c < 16; c++) {
                float p = __expf(Ss[r * FP + q * 16 + c] - mrow);
                Ss[r * FP + q * 16 + c] = p;
                ssum += p;
            }
            red[r * 4 + q] = ssum;
        }
        __syncthreads();
        if (tid < 64)
            ls[tid] += red[tid * 4 + 0] + red[tid * 4 + 1] +
                       red[tid * 4 + 2] + red[tid * 4 + 3];

        float al[4];
#pragma unroll
        for (int i = 0; i < 4; i++) al[i] = aS[ty * 4 + i];
#pragma unroll
        for (int i = 0; i < 4; i++)
#pragma unroll
            for (int j = 0; j < 4; j++) o[i][j] *= al[i];

#pragma unroll 8
        for (int k = 0; k < 64; k++) {
            float p0 = Ss[(ty * 4 + 0) * FP + k];
            float p1 = Ss[(ty * 4 + 1) * FP + k];
            float p2 = Ss[(ty * 4 + 2) * FP + k];
            float p3 = Ss[(ty * 4 + 3) * FP + k];
            float v0 = Vs[k * FP + tx * 4 + 0];
            float v1 = Vs[k * FP + tx * 4 + 1];
            float v2 = Vs[k * FP + tx * 4 + 2];
            float v3 = Vs[k * FP + tx * 4 + 3];
            o[0][0] = fmaf(p0, v0, o[0][0]); o[0][1] = fmaf(p0, v1, o[0][1]);
            o[0][2] = fmaf(p0, v2, o[0][2]); o[0][3] = fmaf(p0, v3, o[0][3]);
            o[1][0] = fmaf(p1, v0, o[1][0]); o[1][1] = fmaf(p1, v1, o[1][1]);
            o[1][2] = fmaf(p1, v2, o[1][2]); o[1][3] = fmaf(p1, v3, o[1][3]);
            o[2][0] = fmaf(p2, v0, o[2][0]); o[2][1] = fmaf(p2, v1, o[2][1]);
            o[2][2] = fmaf(p2, v2, o[2][2]); o[2][3] = fmaf(p2, v3, o[2][3]);
            o[3][0] = fmaf(p3, v0, o[3][0]); o[3][1] = fmaf(p3, v1, o[3][1]);
            o[3][2] = fmaf(p3, v2, o[3][2]); o[3][3] = fmaf(p3, v3, o[3][3]);
        }
        __syncthreads();
    }

    float invl[4];
#pragma unroll
    for (int i = 0; i < 4; i++) invl[i] = 1.f / ls[ty * 4 + i];
#pragma unroll
    for (int i = 0; i < 4; i++)
#pragma unroll
        for (int j = 0; j < 4; j++)
            ctx[baseQ + (size_t)(ty * 4 + i) * D_MODEL + tx * 4 + j] =
                o[i][j] * invl[i];
}

// ---------------------------------------------------------------------------
// LayerNorm over last dim (1024). One block (256 threads) per row.
// ---------------------------------------------------------------------------
__global__ void __launch_bounds__(256)
ln_kernel(const float* __restrict__ x, const float* __restrict__ g,
          const float* __restrict__ bb, float* __restrict__ out)
{
    const int row = blockIdx.x;
    const int tid = threadIdx.x;
    const float4 v = ((const float4*)(x + (size_t)row * D_MODEL))[tid];

    float s  = v.x + v.y + v.z + v.w;
    float ss = fmaf(v.x, v.x, fmaf(v.y, v.y, fmaf(v.z, v.z, v.w * v.w)));

    __shared__ float rs[8], rss[8];
#pragma unroll
    for (int o = 16; o > 0; o >>= 1) {
        s  += __shfl_down_sync(0xFFFFFFFFu, s, o);
        ss += __shfl_down_sync(0xFFFFFFFFu, ss, o);
    }
    if ((tid & 31) == 0) { rs[tid >> 5] = s; rss[tid >> 5] = ss; }
    __syncthreads();
    if (tid == 0) {
        float S = 0.f, SS = 0.f;
#pragma unroll
        for (int i = 0; i < 8; i++) { S += rs[i]; SS += rss[i]; }
        rs[0] = S; rss[0] = SS;
    }
    __syncthreads();

    const float mu  = rs[0] * (1.f / D_MODEL);
    const float var = rss[0] * (1.f / D_MODEL) - mu * mu;
    const float inv = rsqrtf(var + 1e-5f);

    const float4 g4 = ((const float4*)g)[tid];
    const float4 b4 = ((const float4*)bb)[tid];
    float4 o4;
    o4.x = (v.x - mu) * inv * g4.x + b4.x;
    o4.y = (v.y - mu) * inv * g4.y + b4.y;
    o4.z = (v.z - mu) * inv * g4.z + b4.z;
    o4.w = (v.w - mu) * inv * g4.w + b4.w;
    ((float4*)(out + (size_t)row * D_MODEL))[tid] = o4;
}

// ---------------------------------------------------------------------------
// Launcher
// ---------------------------------------------------------------------------
extern "C" void kernel_launch(void* const* d_in, const int* in_sizes, int n_in,
                              void* d_out, int out_size)
{
    const float* src   = (const float*)d_in[0];
    const float* Wq    = (const float*)d_in[1];
    const float* bq    = (const float*)d_in[2];
    const float* Wk    = (const float*)d_in[3];
    const float* bk    = (const float*)d_in[4];
    const float* Wv    = (const float*)d_in[5];
    const float* bv    = (const float*)d_in[6];
    const float* Wo    = (const float*)d_in[7];
    const float* bo    = (const float*)d_in[8];
    const float* W1    = (const float*)d_in[9];
    const float* b1    = (const float*)d_in[10];
    const float* W2    = (const float*)d_in[11];
    const float* b2    = (const float*)d_in[12];
    const float* ln1g  = (const float*)d_in[13];
    const float* ln1b  = (const float*)d_in[14];
    const float* ln2g  = (const float*)d_in[15];
    const float* ln2b  = (const float*)d_in[16];
    float* out = (float*)d_out;

    float *Q, *K, *V, *ctx, *t1, *x1, *h1, *t2;
    cudaGetSymbolAddress((void**)&Q,   g_Q);
    cudaGetSymbolAddress((void**)&K,   g_K);
    cudaGetSymbolAddress((void**)&V,   g_V);
    cudaGetSymbolAddress((void**)&ctx, g_ctx);
    cudaGetSymbolAddress((void**)&t1,  g_t1);
    cudaGetSymbolAddress((void**)&x1,  g_x1);
    cudaGetSymbolAddress((void**)&h1,  g_h1);
    cudaGetSymbolAddress((void**)&t2,  g_t2);

    const int flash_smem = (4 * 64 * FP + 64 * 3 + 64 * 4) * (int)sizeof(float);
    cudaFuncSetAttribute(flash_kernel,
                         cudaFuncAttributeMaxDynamicSharedMemorySize, flash_smem);
    cudaFuncSetAttribute(gemm_tc,
                         cudaFuncAttributeMaxDynamicSharedMemorySize, GEMM_SMEM_BYTES);

    const float qscale = 0.125f;  // 1/sqrt(64)

    dim3 gProj(D_MODEL / BN, MTOT / BM);   // (8, 32)
    dim3 gFF1 (DFF / BN,     MTOT / BM);   // (32, 32)

    // QKV projections (tf32 mma)
    gemm_tc<<<gProj, 256, GEMM_SMEM_BYTES>>>(src, Wq, bq, nullptr, Q, MTOT, D_MODEL, D_MODEL, qscale, 0);
    gemm_tc<<<gProj, 256, GEMM_SMEM_BYTES>>>(src, Wk, bk, nullptr, K, MTOT, D_MODEL, D_MODEL, 1.f, 0);
    gemm_tc<<<gProj, 256, GEMM_SMEM_BYTES>>>(src, Wv, bv, nullptr, V, MTOT, D_MODEL, D_MODEL, 1.f, 0);

    // Attention
    dim3 gAtt(SEQ / 64, NHEADS, BATCH);
    flash_kernel<<<gAtt, 256, flash_smem>>>(Q, K, V, ctx);

    // Output projection + residual, LN1
    gemm_tc<<<gProj, 256, GEMM_SMEM_BYTES>>>(ctx, Wo, bo, src, t1, MTOT, D_MODEL, D_MODEL, 1.f, 0);
    ln_kernel<<<MTOT, 256>>>(t1, ln1g, ln1b, x1);

    // FFN
    gemm_tc<<<gFF1, 256, GEMM_SMEM_BYTES>>>(x1, W1, b1, nullptr, h1, MTOT, DFF, D_MODEL, 1.f, 1);
    gemm_tc<<<gProj, 256, GEMM_SMEM_BYTES>>>(h1, W2, b2, x1, t2, MTOT, D_MODEL, DFF, 1.f, 0);
    ln_kernel<<<MTOT, 256>>>(t2, ln2g, ln2b, out);
}

// round 4
// speedup vs baseline: 2.6039x; 1.4768x over previous
#include <cuda_runtime.h>
#include <cuda_bf16.h>
#include <cstdint>
#include <math.h>

// ---------------------------------------------------------------------------
// EncoderLayer: B=2, S=2048, D=1024, H=16, dk=64, FF=4096, fp32
// Round 4: flash attention moved to mma.sync tf32 (same fragment scheme the
//          passing GEMM validated). GEMM/LN unchanged from Round 3.
// ---------------------------------------------------------------------------

#define D_MODEL 1024
#define SEQ     2048
#define BATCH   2
#define NHEADS  16
#define DK      64
#define DFF     4096
#define MTOT    (BATCH * SEQ)          // 4096 rows

__device__ float g_Q  [MTOT * D_MODEL];
__device__ float g_K  [MTOT * D_MODEL];
__device__ float g_V  [MTOT * D_MODEL];
__device__ float g_ctx[MTOT * D_MODEL];
__device__ float g_t1 [MTOT * D_MODEL];
__device__ float g_x1 [MTOT * D_MODEL];
__device__ float g_h1 [MTOT * DFF];
__device__ float g_t2 [MTOT * D_MODEL];

// ---------------------------------------------------------------------------
// Common PTX helpers
// ---------------------------------------------------------------------------
__device__ __forceinline__ void cp16(uint32_t saddr, const void* gptr) {
    asm volatile("cp.async.cg.shared.global [%0], [%1], 16;"
                 :: "r"(saddr), "l"(gptr));
}
__device__ __forceinline__ uint32_t smem_u32(const void* p) {
    uint32_t a;
    asm("{ .reg .u64 t; cvta.to.shared.u64 t, %1; cvt.u32.u64 %0, t; }"
        : "=r"(a) : "l"(p));
    return a;
}
__device__ __forceinline__ uint32_t to_tf32(float v) {
    uint32_t x;
    asm("cvt.rna.tf32.f32 %0, %1;" : "=r"(x) : "f"(v));
    return x;
}
#define MMA_TF32(acc, a0, a1, a2, a3, b0, b1) \
    asm volatile( \
        "mma.sync.aligned.m16n8k8.row.col.f32.tf32.tf32.f32 " \
        "{%0,%1,%2,%3}, {%4,%5,%6,%7}, {%8,%9}, {%0,%1,%2,%3};" \
        : "+f"((acc)[0]), "+f"((acc)[1]), "+f"((acc)[2]), "+f"((acc)[3]) \
        : "r"(a0), "r"(a1), "r"(a2), "r"(a3), "r"(b0), "r"(b1))

// ---------------------------------------------------------------------------
// tf32 MMA GEMM (unchanged from Round 3, passing)
// ---------------------------------------------------------------------------
#define BM 128
#define BN 128
#define BK 32
#define APITCH 36
#define BPITCH 136
#define A_TILE (BM * APITCH)
#define B_TILE (BK * BPITCH)
#define GEMM_SMEM_BYTES (2 * (A_TILE + B_TILE) * 4)

__global__ void __launch_bounds__(256, 2)
gemm_tc(const float* __restrict__ A, const float* __restrict__ W,
        const float* __restrict__ bias, const float* __restrict__ res,
        float* __restrict__ C, int M, int N, int K, float scale, int relu)
{
    extern __shared__ float sm[];
    float* sA[2] = { sm,              sm + A_TILE };
    float* sB[2] = { sm + 2 * A_TILE, sm + 2 * A_TILE + B_TILE };

    const int tid = threadIdx.x;
    const int wid = tid >> 5;
    const int lid = tid & 31;
    const int g   = lid >> 2;
    const int t   = lid & 3;
    const int wm  = wid >> 2;
    const int wn  = wid & 3;
    const int bm  = blockIdx.y * BM;
    const int bn  = blockIdx.x * BN;

    float acc[4][4][4];
#pragma unroll
    for (int mi = 0; mi < 4; mi++)
#pragma unroll
        for (int ni = 0; ni < 4; ni++)
#pragma unroll
            for (int c = 0; c < 4; c++) acc[mi][ni][c] = 0.f;

    const uint32_t sA_u[2] = { smem_u32(sA[0]), smem_u32(sA[1]) };
    const uint32_t sB_u[2] = { smem_u32(sB[0]), smem_u32(sB[1]) };

    auto load_tiles = [&](int buf, int k0) {
#pragma unroll
        for (int l = 0; l < 4; l++) {
            int c  = tid + l * 256;
            int r  = c >> 3;
            int sg = c & 7;
            cp16(sA_u[buf] + (uint32_t)(r * APITCH + sg * 4) * 4,
                 A + (size_t)(bm + r) * K + k0 + sg * 4);
        }
#pragma unroll
        for (int l = 0; l < 4; l++) {
            int c  = tid + l * 256;
            int r  = c >> 5;
            int sg = c & 31;
            cp16(sB_u[buf] + (uint32_t)(r * BPITCH + sg * 4) * 4,
                 W + (size_t)(k0 + r) * N + bn + sg * 4);
        }
    };

    const int niter = K / BK;
    load_tiles(0, 0);
    asm volatile("cp.async.commit_group;" ::: "memory");

    for (int it = 0; it < niter; it++) {
        asm volatile("cp.async.wait_group 0;" ::: "memory");
        __syncthreads();

        if (it + 1 < niter) load_tiles((it + 1) & 1, (it + 1) * BK);
        asm volatile("cp.async.commit_group;" ::: "memory");

        const float* As = sA[it & 1];
        const float* Bs = sB[it & 1];
        const int mrow = wm * 64;
        const int ncol = wn * 32;

#pragma unroll
        for (int kk = 0; kk < 4; kk++) {
            const int kb = kk * 8;
            uint32_t af[4][4], bf[4][2];
#pragma unroll
            for (int mi = 0; mi < 4; mi++) {
                const float* ap = As + (mrow + mi * 16 + g) * APITCH + kb + t;
                af[mi][0] = to_tf32(ap[0]);
                af[mi][1] = to_tf32(ap[8 * APITCH]);
                af[mi][2] = to_tf32(ap[4]);
                af[mi][3] = to_tf32(ap[8 * APITCH + 4]);
            }
#pragma unroll
            for (int ni = 0; ni < 4; ni++) {
                const float* bp = Bs + (kb + t) * BPITCH + ncol + ni * 8 + g;
                bf[ni][0] = to_tf32(bp[0]);
                bf[ni][1] = to_tf32(bp[4 * BPITCH]);
            }
#pragma unroll
            for (int mi = 0; mi < 4; mi++)
#pragma unroll
                for (int ni = 0; ni < 4; ni++)
                    MMA_TF32(acc[mi][ni], af[mi][0], af[mi][1], af[mi][2],
                             af[mi][3], bf[ni][0], bf[ni][1]);
        }
        __syncthreads();
    }

#pragma unroll
    for (int mi = 0; mi < 4; mi++) {
        const int r0 = bm + wm * 64 + mi * 16 + g;
        const int r1 = r0 + 8;
#pragma unroll
        for (int ni = 0; ni < 4; ni++) {
            const int c0 = bn + wn * 32 + ni * 8 + 2 * t;
            const float b0 = bias[c0], b1 = bias[c0 + 1];

            float v00 = (acc[mi][ni][0] + b0) * scale;
            float v01 = (acc[mi][ni][1] + b1) * scale;
            float v10 = (acc[mi][ni][2] + b0) * scale;
            float v11 = (acc[mi][ni][3] + b1) * scale;
            if (relu) {
                v00 = fmaxf(v00, 0.f); v01 = fmaxf(v01, 0.f);
                v10 = fmaxf(v10, 0.f); v11 = fmaxf(v11, 0.f);
            }
            if (res) {
                float2 q0 = *(const float2*)(res + (size_t)r0 * N + c0);
                float2 q1 = *(const float2*)(res + (size_t)r1 * N + c0);
                v00 += q0.x; v01 += q0.y; v10 += q1.x; v11 += q1.y;
            }
            *(float2*)(C + (size_t)r0 * N + c0) = make_float2(v00, v01);
            *(float2*)(C + (size_t)r1 * N + c0) = make_float2(v10, v11);
        }
    }
}

// ---------------------------------------------------------------------------
// Flash attention on mma.sync tf32.
// CTA: 128 queries x full KV sweep (64-key tiles). 8 warps; warp w owns
// Q rows [w*16, w*16+16). Q frags in registers; K/V cp.async double-buffered;
// P round-trips through per-warp SMEM region for the PV A-fragments.
// ---------------------------------------------------------------------------
#define FBQ 128
#define FBK 64
#define KPITCH 68     // ==4 mod 32: K b-frag banks 4g+t distinct
#define VPITCH 72     // ==8 mod 32: V b-frag banks 8t+g distinct
#define PPITCH 68     // ==4 mod 32: P a-frag banks 4g+t distinct
#define KV_TILE_K (FBK * KPITCH)
#define KV_TILE_V (FBK * VPITCH)
#define FLASH_SMEM ((2 * KV_TILE_K + 2 * KV_TILE_V + FBQ * PPITCH) * 4)

__global__ void __launch_bounds__(256, 1)
flash_tc(const float* __restrict__ Qg, const float* __restrict__ Kg,
         const float* __restrict__ Vg, float* __restrict__ ctx)
{
    extern __shared__ float fs[];
    float* sK[2] = { fs, fs + KV_TILE_K };
    float* sV[2] = { fs + 2 * KV_TILE_K, fs + 2 * KV_TILE_K + KV_TILE_V };
    float* sP    = fs + 2 * KV_TILE_K + 2 * KV_TILE_V;

    const int tid = threadIdx.x;
    const int wid = tid >> 5;
    const int lid = tid & 31;
    const int g   = lid >> 2;
    const int t   = lid & 3;
    const int qb  = blockIdx.x;
    const int h   = blockIdx.y;
    const int b   = blockIdx.z;

    const size_t baseQ  = ((size_t)b * SEQ + (size_t)qb * FBQ) * D_MODEL + h * DK;
    const size_t baseKV = ((size_t)b * SEQ) * D_MODEL + h * DK;

    const uint32_t sK_u[2] = { smem_u32(sK[0]), smem_u32(sK[1]) };
    const uint32_t sV_u[2] = { smem_u32(sV[0]), smem_u32(sV[1]) };

    // ---- stage Q through sP, build register fragments -------------------
    for (int i = tid; i < FBQ * 16; i += 256) {
        int r = i >> 4, c4 = i & 15;
        float4 v = *(const float4*)(Qg + baseQ + (size_t)r * D_MODEL + c4 * 4);
        *(float4*)(&sP[r * PPITCH + c4 * 4]) = v;
    }
    __syncthreads();

    const int qrow = wid * 16;
    uint32_t qf[8][4];
#pragma unroll
    for (int kb = 0; kb < 8; kb++) {
        const float* p0 = &sP[(qrow + g) * PPITCH + kb * 8 + t];
        const float* p1 = &sP[(qrow + g + 8) * PPITCH + kb * 8 + t];
        qf[kb][0] = to_tf32(p0[0]);
        qf[kb][1] = to_tf32(p1[0]);
        qf[kb][2] = to_tf32(p0[4]);
        qf[kb][3] = to_tf32(p1[4]);
    }
    __syncthreads();

    float m0 = -1e30f, m1 = -1e30f, l0 = 0.f, l1 = 0.f;
    float oacc[8][4];
#pragma unroll
    for (int ni = 0; ni < 8; ni++)
#pragma unroll
        for (int c = 0; c < 4; c++) oacc[ni][c] = 0.f;

    auto load_kv = [&](int buf, int k0) {
#pragma unroll
        for (int l = 0; l < 4; l++) {
            int c  = tid + l * 256;
            int r  = c >> 4;
            int c4 = c & 15;
            cp16(sK_u[buf] + (uint32_t)(r * KPITCH + c4 * 4) * 4,
                 Kg + baseKV + (size_t)(k0 + r) * D_MODEL + c4 * 4);
        }
#pragma unroll
        for (int l = 0; l < 4; l++) {
            int c  = tid + l * 256;
            int r  = c >> 4;
            int c4 = c & 15;
            cp16(sV_u[buf] + (uint32_t)(r * VPITCH + c4 * 4) * 4,
                 Vg + baseKV + (size_t)(k0 + r) * D_MODEL + c4 * 4);
        }
    };

    const int nkt = SEQ / FBK;
    load_kv(0, 0);
    asm volatile("cp.async.commit_group;" ::: "memory");

    for (int kt = 0; kt < nkt; kt++) {
        asm volatile("cp.async.wait_group 0;" ::: "memory");
        __syncthreads();
        if (kt + 1 < nkt) load_kv((kt + 1) & 1, (kt + 1) * FBK);
        asm volatile("cp.async.commit_group;" ::: "memory");

        const float* K_ = sK[kt & 1];
        const float* V_ = sV[kt & 1];

        // ---- S = Q @ K^T (16 x 64 per warp) ----------------------------
        float sacc[8][4];
#pragma unroll
        for (int ni = 0; ni < 8; ni++)
#pragma unroll
            for (int c = 0; c < 4; c++) sacc[ni][c] = 0.f;

#pragma unroll
        for (int kb = 0; kb < 8; kb++) {
#pragma unroll
            for (int ni = 0; ni < 8; ni++) {
                const float* kp = &K_[(ni * 8 + g) * KPITCH + kb * 8 + t];
                uint32_t b0 = to_tf32(kp[0]);
                uint32_t b1 = to_tf32(kp[4]);
                MMA_TF32(sacc[ni], qf[kb][0], qf[kb][1], qf[kb][2], qf[kb][3],
                         b0, b1);
            }
        }

        // ---- online softmax (register + shfl only) ---------------------
        float mx0 = -1e30f, mx1 = -1e30f;
#pragma unroll
        for (int ni = 0; ni < 8; ni++) {
            mx0 = fmaxf(mx0, fmaxf(sacc[ni][0], sacc[ni][1]));
            mx1 = fmaxf(mx1, fmaxf(sacc[ni][2], sacc[ni][3]));
        }
        mx0 = fmaxf(mx0, __shfl_xor_sync(0xFFFFFFFFu, mx0, 1));
        mx0 = fmaxf(mx0, __shfl_xor_sync(0xFFFFFFFFu, mx0, 2));
        mx1 = fmaxf(mx1, __shfl_xor_sync(0xFFFFFFFFu, mx1, 1));
        mx1 = fmaxf(mx1, __shfl_xor_sync(0xFFFFFFFFu, mx1, 2));

        const float mn0 = fmaxf(m0, mx0);
        const float mn1 = fmaxf(m1, mx1);
        const float al0 = __expf(m0 - mn0);
        const float al1 = __expf(m1 - mn1);
        m0 = mn0; m1 = mn1;

        float s0 = 0.f, s1 = 0.f;
#pragma unroll
        for (int ni = 0; ni < 8; ni++) {
            float p00 = __expf(sacc[ni][0] - mn0);
            float p01 = __expf(sacc[ni][1] - mn0);
            float p10 = __expf(sacc[ni][2] - mn1);
            float p11 = __expf(sacc[ni][3] - mn1);
            s0 += p00 + p01;
            s1 += p10 + p11;
            *(float2*)(&sP[(qrow + g) * PPITCH + ni * 8 + 2 * t]) =
                make_float2(p00, p01);
            *(float2*)(&sP[(qrow + g + 8) * PPITCH + ni * 8 + 2 * t]) =
                make_float2(p10, p11);
        }
        s0 += __shfl_xor_sync(0xFFFFFFFFu, s0, 1);
        s0 += __shfl_xor_sync(0xFFFFFFFFu, s0, 2);
        s1 += __shfl_xor_sync(0xFFFFFFFFu, s1, 1);
        s1 += __shfl_xor_sync(0xFFFFFFFFu, s1, 2);
        l0 = l0 * al0 + s0;
        l1 = l1 * al1 + s1;

#pragma unroll
        for (int ni = 0; ni < 8; ni++) {
            oacc[ni][0] *= al0; oacc[ni][1] *= al0;
            oacc[ni][2] *= al1; oacc[ni][3] *= al1;
        }
        __syncwarp();

        // ---- O += P @ V ------------------------------------------------
#pragma unroll
        for (int kb = 0; kb < 8; kb++) {
            const float* p0 = &sP[(qrow + g) * PPITCH + kb * 8 + t];
            const float* p1 = &sP[(qrow + g + 8) * PPITCH + kb * 8 + t];
            uint32_t af0 = to_tf32(p0[0]);
            uint32_t af1 = to_tf32(p1[0]);
            uint32_t af2 = to_tf32(p0[4]);
            uint32_t af3 = to_tf32(p1[4]);
#pragma unroll
            for (int ni = 0; ni < 8; ni++) {
                const float* vp = &V_[(kb * 8 + t) * VPITCH + ni * 8 + g];
                uint32_t b0 = to_tf32(vp[0]);
                uint32_t b1 = to_tf32(vp[4 * VPITCH]);
                MMA_TF32(oacc[ni], af0, af1, af2, af3, b0, b1);
            }
        }
    }

    // ---- epilogue -------------------------------------------------------
    const float inv0 = 1.f / l0;
    const float inv1 = 1.f / l1;
#pragma unroll
    for (int ni = 0; ni < 8; ni++) {
        const int c0 = ni * 8 + 2 * t;
        *(float2*)(ctx + baseQ + (size_t)(qrow + g) * D_MODEL + c0) =
            make_float2(oacc[ni][0] * inv0, oacc[ni][1] * inv0);
        *(float2*)(ctx + baseQ + (size_t)(qrow + g + 8) * D_MODEL + c0) =
            make_float2(oacc[ni][2] * inv1, oacc[ni][3] * inv1);
    }
}

// ---------------------------------------------------------------------------
// LayerNorm over last dim (1024). One block (256 threads) per row.
// ---------------------------------------------------------------------------
__global__ void __launch_bounds__(256)
ln_kernel(const float* __restrict__ x, const float* __restrict__ g,
          const float* __restrict__ bb, float* __restrict__ out)
{
    const int row = blockIdx.x;
    const int tid = threadIdx.x;
    const float4 v = ((const float4*)(x + (size_t)row * D_MODEL))[tid];

    float s  = v.x + v.y + v.z + v.w;
    float ss = fmaf(v.x, v.x, fmaf(v.y, v.y, fmaf(v.z, v.z, v.w * v.w)));

    __shared__ float rs[8], rss[8];
#pragma unroll
    for (int o = 16; o > 0; o >>= 1) {
        s  += __shfl_down_sync(0xFFFFFFFFu, s, o);
        ss += __shfl_down_sync(0xFFFFFFFFu, ss, o);
    }
    if ((tid & 31) == 0) { rs[tid >> 5] = s; rss[tid >> 5] = ss; }
    __syncthreads();
    if (tid == 0) {
        float S = 0.f, SS = 0.f;
#pragma unroll
        for (int i = 0; i < 8; i++) { S += rs[i]; SS += rss[i]; }
        rs[0] = S; rss[0] = SS;
    }
    __syncthreads();

    const float mu  = rs[0] * (1.f / D_MODEL);
    const float var = rss[0] * (1.f / D_MODEL) - mu * mu;
    const float inv = rsqrtf(var + 1e-5f);

    const float4 g4 = ((const float4*)g)[tid];
    const float4 b4 = ((const float4*)bb)[tid];
    float4 o4;
    o4.x = (v.x - mu) * inv * g4.x + b4.x;
    o4.y = (v.y - mu) * inv * g4.y + b4.y;
    o4.z = (v.z - mu) * inv * g4.z + b4.z;
    o4.w = (v.w - mu) * inv * g4.w + b4.w;
    ((float4*)(out + (size_t)row * D_MODEL))[tid] = o4;
}

// ---------------------------------------------------------------------------
// Launcher
// ---------------------------------------------------------------------------
extern "C" void kernel_launch(void* const* d_in, const int* in_sizes, int n_in,
                              void* d_out, int out_size)
{
    const float* src   = (const float*)d_in[0];
    const float* Wq    = (const float*)d_in[1];
    const float* bq    = (const float*)d_in[2];
    const float* Wk    = (const float*)d_in[3];
    const float* bk    = (const float*)d_in[4];
    const float* Wv    = (const float*)d_in[5];
    const float* bv    = (const float*)d_in[6];
    const float* Wo    = (const float*)d_in[7];
    const float* bo    = (const float*)d_in[8];
    const float* W1    = (const float*)d_in[9];
    const float* b1    = (const float*)d_in[10];
    const float* W2    = (const float*)d_in[11];
    const float* b2    = (const float*)d_in[12];
    const float* ln1g  = (const float*)d_in[13];
    const float* ln1b  = (const float*)d_in[14];
    const float* ln2g  = (const float*)d_in[15];
    const float* ln2b  = (const float*)d_in[16];
    float* out = (float*)d_out;

    float *Q, *K, *V, *ctx, *t1, *x1, *h1, *t2;
    cudaGetSymbolAddress((void**)&Q,   g_Q);
    cudaGetSymbolAddress((void**)&K,   g_K);
    cudaGetSymbolAddress((void**)&V,   g_V);
    cudaGetSymbolAddress((void**)&ctx, g_ctx);
    cudaGetSymbolAddress((void**)&t1,  g_t1);
    cudaGetSymbolAddress((void**)&x1,  g_x1);
    cudaGetSymbolAddress((void**)&h1,  g_h1);
    cudaGetSymbolAddress((void**)&t2,  g_t2);

    cudaFuncSetAttribute(gemm_tc,
                         cudaFuncAttributeMaxDynamicSharedMemorySize, GEMM_SMEM_BYTES);
    cudaFuncSetAttribute(flash_tc,
                         cudaFuncAttributeMaxDynamicSharedMemorySize, FLASH_SMEM);

    const float qscale = 0.125f;  // 1/sqrt(64)

    dim3 gProj(D_MODEL / BN, MTOT / BM);   // (8, 32)
    dim3 gFF1 (DFF / BN,     MTOT / BM);   // (32, 32)

    gemm_tc<<<gProj, 256, GEMM_SMEM_BYTES>>>(src, Wq, bq, nullptr, Q, MTOT, D_MODEL, D_MODEL, qscale, 0);
    gemm_tc<<<gProj, 256, GEMM_SMEM_BYTES>>>(src, Wk, bk, nullptr, K, MTOT, D_MODEL, D_MODEL, 1.f, 0);
    gemm_tc<<<gProj, 256, GEMM_SMEM_BYTES>>>(src, Wv, bv, nullptr, V, MTOT, D_MODEL, D_MODEL, 1.f, 0);

    dim3 gAtt(SEQ / FBQ, NHEADS, BATCH);   // (16, 16, 2)
    flash_tc<<<gAtt, 256, FLASH_SMEM>>>(Q, K, V, ctx);

    gemm_tc<<<gProj, 256, GEMM_SMEM_BYTES>>>(ctx, Wo, bo, src, t1, MTOT, D_MODEL, D_MODEL, 1.f, 0);
    ln_kernel<<<MTOT, 256>>>(t1, ln1g, ln1b, x1);

    gemm_tc<<<gFF1, 256, GEMM_SMEM_BYTES>>>(x1, W1, b1, nullptr, h1, MTOT, DFF, D_MODEL, 1.f, 1);
    gemm_tc<<<gProj, 256, GEMM_SMEM_BYTES>>>(h1, W2, b2, x1, t2, MTOT, D_MODEL, DFF, 1.f, 0);
    ln_kernel<<<MTOT, 256>>>(t2, ln2g, ln2b, out);
}